// round 8
// baseline (speedup 1.0000x reference)
#include <cuda_runtime.h>

#define N_NODES 16384
#define N_EDGES 262144

typedef unsigned long long ull;

// ---------------------------------------------------------------------------
// Static device scratch (no runtime allocation). NOTE: g_cnt is zero at module
// load and re-zeroed by down_kernel at the end of every launch sequence, so
// hist can run in the first kernel without a separate zeroing pass.
// ---------------------------------------------------------------------------
__device__ float  g_up[N_NODES * 128];     // [n][lane][4] = (s1, v1x, v1y, v1z)
__device__ float  g_acc[N_NODES * 256];    // [n][lane][8] = (S0,S1,V0l,V0h,V1l,V1h,V2l,V2h)
__device__ int    g_cnt[N_NODES];
__device__ int    g_cursor[N_NODES];
__device__ int    g_base;
__device__ int2   g_shdr[N_EDGES];         // sorted header: (snd, rcv<<18 | e)
__device__ float2 g_pUp[1024];             // packed (W_up_s, W_up_v)
__device__ float2 g_pDn2[2048];            // packed (W_dn_s[m][k], W_dn_s[m][32+k])
__device__ float  g_pDnV[2048];            // W_dn_v[m][k]
__device__ float4 g_pSk[4096];             // packed skip weights per species

__device__ __forceinline__ float silu_f(float x) {
    return x / (1.0f + __expf(-x));
}

__device__ __forceinline__ ull pk2(float a, float b) {
    ull r; asm("mov.b64 %0, {%1,%2};" : "=l"(r) : "f"(a), "f"(b)); return r;
}
__device__ __forceinline__ void upk2(float& a, float& b, ull v) {
    asm("mov.b64 {%0,%1}, %2;" : "=f"(a), "=f"(b) : "l"(v));
}
__device__ __forceinline__ ull fma2_(ull a, ull b, ull c) {
    ull d; asm("fma.rn.f32x2 %0, %1, %2, %3;" : "=l"(d) : "l"(a), "l"(b), "l"(c)); return d;
}

// ---------------------------------------------------------------------------
// K1: weight packing (blocks 0..27) + receiver histogram (blocks 28..1051).
// g_cnt is guaranteed zero at entry (zero-init at load; re-zeroed by down).
// ---------------------------------------------------------------------------
__global__ void __launch_bounds__(256)
prep_hist_kernel(const float* __restrict__ Wus, const float* __restrict__ Wuv,
                 const float* __restrict__ Wds, const float* __restrict__ Wdv,
                 const float* __restrict__ Wss, const float* __restrict__ Wsv,
                 const int* __restrict__ rcv) {
    int b = blockIdx.x;
    if (b >= 28) {
        int e = (b - 28) * 256 + threadIdx.x;
        atomicAdd(&g_cnt[rcv[e]], 1);
        return;
    }
    int t = b * 256 + threadIdx.x;
    if (t == 0) g_base = 0;
    if (t < 1024) g_pUp[t] = make_float2(Wus[t], Wuv[t]);
    int i = t - 1024;
    if (i >= 0 && i < 2048) {
        int m = i >> 5, k = i & 31;
        g_pDn2[i] = make_float2(Wds[m * 64 + k], Wds[m * 64 + 32 + k]);
        g_pDnV[i] = Wdv[i];
    }
    int j = t - 3072;
    if (j >= 0 && j < 4096) {
        int sp = j >> 10, q = j & 1023, m = q >> 5, k = q & 31;
        g_pSk[j] = make_float4(Wss[sp * 2048 + m * 64 + k],
                               Wss[sp * 2048 + m * 64 + 32 + k],
                               Wsv[sp * 1024 + q], 0.f);
    }
}

// ---------------------------------------------------------------------------
// K2 parallel scan: block-local scan + atomic global base (arbitrary block
// order is fine — runs only need contiguity, not node order)
// ---------------------------------------------------------------------------
__global__ void __launch_bounds__(256) scan_kernel() {
    __shared__ int sWarp[8];
    __shared__ int sBase;
    int t = threadIdx.x;
    int lane = t & 31, warp = t >> 5;
    int n = blockIdx.x * 256 + t;
    int c = g_cnt[n];
    int incl = c;
    #pragma unroll
    for (int o = 1; o < 32; o <<= 1) {
        int v = __shfl_up_sync(0xffffffffu, incl, o);
        if (lane >= o) incl += v;
    }
    if (lane == 31) sWarp[warp] = incl;
    __syncthreads();
    if (t < 8) {
        int v = sWarp[t];
        #pragma unroll
        for (int o = 1; o < 8; o <<= 1) {
            int u = __shfl_up_sync(0xffu, v, o);
            if (t >= o) v += u;
        }
        sWarp[t] = v;
        if (t == 7) sBase = atomicAdd(&g_base, v);
    }
    __syncthreads();
    int warpBase = (warp > 0) ? sWarp[warp - 1] : 0;
    g_cursor[n] = sBase + warpBase + incl - c;
}

// ---------------------------------------------------------------------------
// K3 fused: scatter (blocks 0..1023) + zero_acc (1024..5119) + up (5120..7167)
// ---------------------------------------------------------------------------
__global__ void __launch_bounds__(256)
mid_kernel(const float* __restrict__ nf,
           const int* __restrict__ receivers, const int* __restrict__ senders) {
    int b = blockIdx.x;
    int t = threadIdx.x;
    if (b < 1024) {                                   // 8B-header scatter
        int e = b * 256 + t;
        int r = receivers[e];
        int s = senders[e];
        int p = atomicAdd(&g_cursor[r], 1);
        g_shdr[p] = make_int2(s, (r << 18) | e);
        return;
    }
    if (b < 5120) {                                   // zero accumulator (16 MB)
        ((float4*)g_acc)[(b - 1024) * 256 + t] = make_float4(0.f, 0.f, 0.f, 0.f);
        return;
    }
    // up-projection: 8 nodes per block (warp per node), packed weights
    __shared__ float2 sWu[1024];
    __shared__ float4 sF[8][32];
    for (int i = t; i < 1024; i += 256) sWu[i] = g_pUp[i];
    __syncthreads();
    int warp = t >> 5, lane = t & 31;
    int n = (b - 5120) * 8 + warp;
    const float* f = nf + (size_t)n * 128;
    sF[warp][lane] = make_float4(f[lane], f[32 + 3 * lane],
                                 f[33 + 3 * lane], f[34 + 3 * lane]);
    __syncwarp();
    float os = 0.f, o0 = 0.f, o1 = 0.f, o2 = 0.f;
    #pragma unroll 8
    for (int m = 0; m < 32; m++) {
        float4 v = sF[warp][m];
        float2 w = sWu[m * 32 + lane];
        os = fmaf(v.x, w.x, os);
        o0 = fmaf(v.y, w.y, o0);
        o1 = fmaf(v.z, w.y, o1);
        o2 = fmaf(v.w, w.y, o2);
    }
    const float S = 0.17677669529663687f;
    ((float4*)g_up)[n * 32 + lane] = make_float4(os * S, o0 * S, o1 * S, o2 * S);
}

// ---------------------------------------------------------------------------
// K4 edge kernel: warp handles 32 receiver-sorted edges.
// SMEM broadcast staging (LDS.128) instead of shuffles; boundary ballot;
// pair-dot w-matvec with register W_r2; ST for interior runs, RED for
// window-straddling first/last runs (g_acc pre-zeroed).
// ---------------------------------------------------------------------------
__global__ void __launch_bounds__(256)
edge_kernel(const float* __restrict__ W_r1, const float* __restrict__ W_r2,
            const float* __restrict__ esh, const float* __restrict__ rad) {
    __shared__ float4 sHY[8][32];    // per warp: (snd_bits, y0, y1, y2) per edge
    __shared__ float  sH[8][256];    // per warp: h[edge][j]
    int t = threadIdx.x, warp = t >> 5, lane = t & 31, j8 = lane & 7;
    int p0 = (blockIdx.x * 8 + warp) * 32;

    const float INV_SQRT8 = 0.3535533905932738f;
    const float SC = INV_SQRT8 * 0.25f;          // radial scale * AVG_NEIGH^-0.5
    const float INV_SQRT3 = 0.5773502691896258f;

    // register-resident W_r2 packed by j-pairs: wp[p][c] = (W2[2p, c*32+lane],
    // W2[2p+1, c*32+lane]) * scale_c  (c==3 carries INV_SQRT3)
    ull wp[4][4];
    #pragma unroll
    for (int p = 0; p < 4; p++) {
        #pragma unroll
        for (int c = 0; c < 4; c++) {
            float scc = (c == 3) ? SC * INV_SQRT3 : SC;
            wp[p][c] = pk2(__ldg(&W_r2[(2 * p) * 128 + c * 32 + lane]) * scc,
                           __ldg(&W_r2[(2 * p + 1) * 128 + c * 32 + lane]) * scc);
        }
    }
    float W1r[8];
    #pragma unroll
    for (int k = 0; k < 8; k++) W1r[k] = __ldg(&W_r1[k * 8 + j8]);

    // full-warp header load + payload gather
    int2 hdr = g_shdr[p0 + lane];
    int e = hdr.y & 0x3FFFF;
    float4 shq = __ldg(&((const float4*)esh)[e]);
    float4 rq0 = __ldg(&((const float4*)rad)[e * 2]);
    float4 rq1 = __ldg(&((const float4*)rad)[e * 2 + 1]);
    sHY[warp][lane] = make_float4(__int_as_float(hdr.x), shq.y, shq.z, shq.w);

    // run-boundary ballot (uniform across warp)
    int r = (int)(((unsigned)hdr.y) >> 18);
    int rprev = __shfl_up_sync(0xffffffffu, r, 1);
    unsigned bnd = __ballot_sync(0xffffffffu, (lane > 0) && (r != rprev));

    // batched radial MLP -> SMEM: sH[warp][b*32 + lane] = h[edge b*4+(lane>>3)][lane&7]
    int el4 = lane >> 3;
    #pragma unroll
    for (int b = 0; b < 8; b++) {
        int src = b * 4 + el4;
        float pre;
        pre = W1r[0] * __shfl_sync(0xffffffffu, rq0.x, src);
        pre = fmaf(W1r[1], __shfl_sync(0xffffffffu, rq0.y, src), pre);
        pre = fmaf(W1r[2], __shfl_sync(0xffffffffu, rq0.z, src), pre);
        pre = fmaf(W1r[3], __shfl_sync(0xffffffffu, rq0.w, src), pre);
        pre = fmaf(W1r[4], __shfl_sync(0xffffffffu, rq1.x, src), pre);
        pre = fmaf(W1r[5], __shfl_sync(0xffffffffu, rq1.y, src), pre);
        pre = fmaf(W1r[6], __shfl_sync(0xffffffffu, rq1.z, src), pre);
        pre = fmaf(W1r[7], __shfl_sync(0xffffffffu, rq1.w, src), pre);
        sH[warp][b * 32 + lane] = silu_f(pre * INV_SQRT8);
    }
    __syncwarp();

    float aS0 = 0.f, aS1 = 0.f;
    float aV0l = 0.f, aV0h = 0.f, aV1l = 0.f, aV1h = 0.f, aV2l = 0.f, aV2h = 0.f;
    int nflush = 0;

    auto flushTo = [&](int node, bool useRed) {
        float* dst = g_acc + (size_t)node * 256 + lane * 8;
        if (useRed) {
            asm volatile("red.global.add.v4.f32 [%0], {%1,%2,%3,%4};"
                         :: "l"(dst), "f"(aS0), "f"(aS1), "f"(aV0l), "f"(aV0h) : "memory");
            asm volatile("red.global.add.v4.f32 [%0], {%1,%2,%3,%4};"
                         :: "l"(dst + 4), "f"(aV1l), "f"(aV1h), "f"(aV2l), "f"(aV2h) : "memory");
        } else {
            asm volatile("st.global.v4.f32 [%0], {%1,%2,%3,%4};"
                         :: "l"(dst), "f"(aS0), "f"(aS1), "f"(aV0l), "f"(aV0h) : "memory");
            asm volatile("st.global.v4.f32 [%0], {%1,%2,%3,%4};"
                         :: "l"(dst + 4), "f"(aV1l), "f"(aV1h), "f"(aV2l), "f"(aV2h) : "memory");
        }
    };

    #pragma unroll
    for (int i = 0; i < 32; i++) {
        if (i > 0 && ((bnd >> i) & 1u)) {
            int node = __shfl_sync(0xffffffffu, r, i - 1);
            flushTo(node, nflush == 0);   // first run may straddle backward -> RED
            nflush++;
            aS0 = aS1 = aV0l = aV0h = aV1l = aV1h = aV2l = aV2h = 0.f;
        }
        float4 hy = sHY[warp][i];                       // uniform LDS.128
        int snd = __float_as_int(hy.x);
        float4 u = __ldg(&((const float4*)g_up)[snd * 32 + lane]);

        const float4* hp4 = (const float4*)&sH[warp][i * 8];
        float4 ha = hp4[0];                             // h0..h3 (uniform LDS.128)
        float4 hc = hp4[1];                             // h4..h7
        ull h01 = pk2(ha.x, ha.y), h23 = pk2(ha.z, ha.w);
        ull h45 = pk2(hc.x, hc.y), h67 = pk2(hc.z, hc.w);

        ull a0 = 0, a1 = 0, a2 = 0, a3 = 0;
        a0 = fma2_(h01, wp[0][0], a0); a1 = fma2_(h01, wp[0][1], a1);
        a2 = fma2_(h01, wp[0][2], a2); a3 = fma2_(h01, wp[0][3], a3);
        a0 = fma2_(h23, wp[1][0], a0); a1 = fma2_(h23, wp[1][1], a1);
        a2 = fma2_(h23, wp[1][2], a2); a3 = fma2_(h23, wp[1][3], a3);
        a0 = fma2_(h45, wp[2][0], a0); a1 = fma2_(h45, wp[2][1], a1);
        a2 = fma2_(h45, wp[2][2], a2); a3 = fma2_(h45, wp[2][3], a3);
        a0 = fma2_(h67, wp[3][0], a0); a1 = fma2_(h67, wp[3][1], a1);
        a2 = fma2_(h67, wp[3][2], a2); a3 = fma2_(h67, wp[3][3], a3);

        float w0, w1, w2, w3, lo, hi;
        upk2(lo, hi, a0); w0 = lo + hi;
        upk2(lo, hi, a1); w1 = lo + hi;
        upk2(lo, hi, a2); w2 = lo + hi;
        upk2(lo, hi, a3); w3 = lo + hi;

        float dot = u.y * hy.y;
        dot = fmaf(u.z, hy.z, dot);
        dot = fmaf(u.w, hy.w, dot);
        float sst = u.x * w2;

        aS0  = fmaf(u.x, w0, aS0);
        aS1  = fmaf(dot, w3, aS1);
        aV0l = fmaf(u.y, w1, aV0l);  aV0h = fmaf(sst, hy.y, aV0h);
        aV1l = fmaf(u.z, w1, aV1l);  aV1h = fmaf(sst, hy.z, aV1h);
        aV2l = fmaf(u.w, w1, aV2l);  aV2h = fmaf(sst, hy.w, aV2h);
    }
    int lastnode = __shfl_sync(0xffffffffu, r, 31);
    flushTo(lastnode, true);   // last run may straddle forward -> RED
}

// ---------------------------------------------------------------------------
// K5 down-projection + skip + gating: 4 nodes per warp, __ldg weights,
// f32x2 accumulation. Also re-zeroes g_cnt for the next launch sequence.
// ---------------------------------------------------------------------------
__global__ void __launch_bounds__(128)
down_kernel(const float* __restrict__ nf,
            const int* __restrict__ species,
            float* __restrict__ out) {
    __shared__ float4 st[4][4][96];   // [warp][node][0:64 columns | 64:96 nf]
    int t = threadIdx.x, warp = t >> 5, lane = t & 31;
    int gid = blockIdx.x * 128 + t;
    if (gid < N_NODES) g_cnt[gid] = 0;     // restore invariant for next call
    int n0 = blockIdx.x * 16 + warp * 4;

    #pragma unroll
    for (int u = 0; u < 4; u++) {
        int n = n0 + u;
        const float4* a4 = (const float4*)g_acc + (size_t)n * 64;
        float4 qa = a4[lane * 2];
        float4 qb = a4[lane * 2 + 1];
        st[warp][u][lane]      = make_float4(qa.x, qa.z, qb.x, qb.z);  // cols m=lane
        st[warp][u][32 + lane] = make_float4(qa.y, qa.w, qb.y, qb.w);  // cols m=32+lane
        const float* f = nf + (size_t)n * 128;
        st[warp][u][64 + lane] = make_float4(f[lane], f[32 + 3 * lane],
                                             f[33 + 3 * lane], f[34 + 3 * lane]);
    }
    __syncwarp();

    const ull* w2p = (const ull*)g_pDn2;
    ull g01[4] = {0, 0, 0, 0}, gv[4] = {0, 0, 0, 0};
    float g4[4] = {0.f, 0.f, 0.f, 0.f};
    #pragma unroll 4
    for (int m = 0; m < 64; m++) {
        ull w2 = __ldg(&w2p[m * 32 + lane]);
        float wv = __ldg(&g_pDnV[m * 32 + lane]);
        ull wv2 = pk2(wv, wv);
        #pragma unroll
        for (int u = 0; u < 4; u++) {
            float4 b = st[warp][u][m];
            g01[u] = fma2_(pk2(b.x, b.x), w2, g01[u]);
            gv[u]  = fma2_(pk2(b.y, b.z), wv2, gv[u]);
            g4[u]  = fmaf(b.w, wv, g4[u]);
        }
    }

    int sp[4];
    #pragma unroll
    for (int u = 0; u < 4; u++) sp[u] = species[n0 + u];

    ull s01[4] = {0, 0, 0, 0}, sv[4] = {0, 0, 0, 0};
    float s4[4] = {0.f, 0.f, 0.f, 0.f};
    #pragma unroll 4
    for (int m = 0; m < 32; m++) {
        #pragma unroll
        for (int u = 0; u < 4; u++) {
            float4 w = __ldg(&g_pSk[sp[u] * 1024 + m * 32 + lane]);
            float4 c = st[warp][u][64 + m];
            s01[u] = fma2_(pk2(c.x, c.x), pk2(w.x, w.y), s01[u]);
            sv[u]  = fma2_(pk2(c.y, c.z), pk2(w.z, w.z), sv[u]);
            s4[u]  = fmaf(c.w, w.z, s4[u]);
        }
    }

    const float A = 0.5f * 0.125f;                 // 0.5 * (2*MUL)^-0.5
    const float B = 0.5f * 0.17677669529663687f;   // 0.5 * MUL^-0.5

    #pragma unroll
    for (int u = 0; u < 4; u++) {
        float G0, G1, H0, H1, S0, S1, T0, T1;
        upk2(G0, G1, g01[u]);
        upk2(H0, H1, gv[u]);
        upk2(S0, S1, s01[u]);
        upk2(T0, T1, sv[u]);
        G0 = G0 * A + S0 * B;
        G1 = G1 * A + S1 * B;
        H0 = H0 * A + T0 * B;
        H1 = H1 * A + T1 * B;
        float H2 = g4[u] * A + s4[u] * B;
        float feat = silu_f(G0);
        float gate = silu_f(G1);
        float* o = out + (size_t)(n0 + u) * 128;
        o[lane] = feat;
        o[32 + lane * 3 + 0] = H0 * gate;
        o[32 + lane * 3 + 1] = H1 * gate;
        o[32 + lane * 3 + 2] = H2 * gate;
    }
}

// ---------------------------------------------------------------------------
extern "C" void kernel_launch(void* const* d_in, const int* in_sizes, int n_in,
                              void* d_out, int out_size) {
    const float* nf  = (const float*)d_in[0];
    const float* esh = (const float*)d_in[1];
    const float* rad = (const float*)d_in[2];
    const float* Wus = (const float*)d_in[3];
    const float* Wuv = (const float*)d_in[4];
    const float* Wr1 = (const float*)d_in[5];
    const float* Wr2 = (const float*)d_in[6];
    const float* Wds = (const float*)d_in[7];
    const float* Wdv = (const float*)d_in[8];
    const float* Wss = (const float*)d_in[9];
    const float* Wsv = (const float*)d_in[10];
    const int* snd  = (const int*)d_in[11];
    const int* rcv  = (const int*)d_in[12];
    const int* spec = (const int*)d_in[13];
    float* out = (float*)d_out;

    prep_hist_kernel<<<1052, 256>>>(Wus, Wuv, Wds, Wdv, Wss, Wsv, rcv);
    scan_kernel<<<64, 256>>>();
    mid_kernel<<<7168, 256>>>(nf, rcv, snd);
    edge_kernel<<<1024, 256>>>(Wr1, Wr2, esh, rad);
    down_kernel<<<1024, 128>>>(nf, spec, out);
}

// round 9
// speedup vs baseline: 1.0622x; 1.0622x over previous
#include <cuda_runtime.h>

#define N_NODES 16384
#define N_EDGES 262144

typedef unsigned long long ull;

// ---------------------------------------------------------------------------
// Static device scratch (no runtime allocation). NOTE: g_cnt is zero at module
// load and re-zeroed by down_kernel at the end of every launch sequence, so
// hist can run in the first kernel without a separate zeroing pass.
// ---------------------------------------------------------------------------
__device__ float  g_up[N_NODES * 128];     // [n][lane][4] = (s1, v1x, v1y, v1z)
__device__ float  g_acc[N_NODES * 256];    // [n][lane][8] = (S0,S1,V0l,V0h,V1l,V1h,V2l,V2h)
__device__ int    g_cnt[N_NODES];
__device__ int    g_cursor[N_NODES];
__device__ int    g_base;
__device__ int2   g_shdr[N_EDGES];         // sorted header: (snd, rcv<<18 | e)
__device__ float2 g_pUp[1024];             // packed (W_up_s, W_up_v)
__device__ float2 g_pDn2[2048];            // packed (W_dn_s[m][k], W_dn_s[m][32+k])
__device__ float  g_pDnV[2048];            // W_dn_v[m][k]
__device__ float4 g_pSk[4096];             // packed skip weights per species

__device__ __forceinline__ float silu_f(float x) {
    return x / (1.0f + __expf(-x));
}

__device__ __forceinline__ ull pk2(float a, float b) {
    ull r; asm("mov.b64 %0, {%1,%2};" : "=l"(r) : "f"(a), "f"(b)); return r;
}
__device__ __forceinline__ void upk2(float& a, float& b, ull v) {
    asm("mov.b64 {%0,%1}, %2;" : "=f"(a), "=f"(b) : "l"(v));
}
__device__ __forceinline__ ull fma2_(ull a, ull b, ull c) {
    ull d; asm("fma.rn.f32x2 %0, %1, %2, %3;" : "=l"(d) : "l"(a), "l"(b), "l"(c)); return d;
}

// ---------------------------------------------------------------------------
// K1: weight packing (blocks 0..27) + receiver histogram (blocks 28..1051).
// g_cnt is guaranteed zero at entry (zero-init at load; re-zeroed by down).
// ---------------------------------------------------------------------------
__global__ void __launch_bounds__(256)
prep_hist_kernel(const float* __restrict__ Wus, const float* __restrict__ Wuv,
                 const float* __restrict__ Wds, const float* __restrict__ Wdv,
                 const float* __restrict__ Wss, const float* __restrict__ Wsv,
                 const int* __restrict__ rcv) {
    int b = blockIdx.x;
    if (b >= 28) {
        int e = (b - 28) * 256 + threadIdx.x;
        atomicAdd(&g_cnt[rcv[e]], 1);
        return;
    }
    int t = b * 256 + threadIdx.x;
    if (t == 0) g_base = 0;
    if (t < 1024) g_pUp[t] = make_float2(Wus[t], Wuv[t]);
    int i = t - 1024;
    if (i >= 0 && i < 2048) {
        int m = i >> 5, k = i & 31;
        g_pDn2[i] = make_float2(Wds[m * 64 + k], Wds[m * 64 + 32 + k]);
        g_pDnV[i] = Wdv[i];
    }
    int j = t - 3072;
    if (j >= 0 && j < 4096) {
        int sp = j >> 10, q = j & 1023, m = q >> 5, k = q & 31;
        g_pSk[j] = make_float4(Wss[sp * 2048 + m * 64 + k],
                               Wss[sp * 2048 + m * 64 + 32 + k],
                               Wsv[sp * 1024 + q], 0.f);
    }
}

// ---------------------------------------------------------------------------
// K2 parallel scan: block-local scan + atomic global base (arbitrary block
// order is fine — runs only need contiguity, not node order)
// ---------------------------------------------------------------------------
__global__ void __launch_bounds__(256) scan_kernel() {
    __shared__ int sWarp[8];
    __shared__ int sBase;
    int t = threadIdx.x;
    int lane = t & 31, warp = t >> 5;
    int n = blockIdx.x * 256 + t;
    int c = g_cnt[n];
    int incl = c;
    #pragma unroll
    for (int o = 1; o < 32; o <<= 1) {
        int v = __shfl_up_sync(0xffffffffu, incl, o);
        if (lane >= o) incl += v;
    }
    if (lane == 31) sWarp[warp] = incl;
    __syncthreads();
    if (t < 8) {
        int v = sWarp[t];
        #pragma unroll
        for (int o = 1; o < 8; o <<= 1) {
            int u = __shfl_up_sync(0xffu, v, o);
            if (t >= o) v += u;
        }
        sWarp[t] = v;
        if (t == 7) sBase = atomicAdd(&g_base, v);
    }
    __syncthreads();
    int warpBase = (warp > 0) ? sWarp[warp - 1] : 0;
    g_cursor[n] = sBase + warpBase + incl - c;
}

// ---------------------------------------------------------------------------
// K3 fused: scatter (blocks 0..1023) + zero_acc (1024..5119) + up (5120..7167)
// ---------------------------------------------------------------------------
__global__ void __launch_bounds__(256)
mid_kernel(const float* __restrict__ nf,
           const int* __restrict__ receivers, const int* __restrict__ senders) {
    int b = blockIdx.x;
    int t = threadIdx.x;
    if (b < 1024) {                                   // 8B-header scatter
        int e = b * 256 + t;
        int r = receivers[e];
        int s = senders[e];
        int p = atomicAdd(&g_cursor[r], 1);
        g_shdr[p] = make_int2(s, (r << 18) | e);
        return;
    }
    if (b < 5120) {                                   // zero accumulator (16 MB)
        ((float4*)g_acc)[(b - 1024) * 256 + t] = make_float4(0.f, 0.f, 0.f, 0.f);
        return;
    }
    // up-projection: 8 nodes per block (warp per node), packed weights
    __shared__ float2 sWu[1024];
    __shared__ float4 sF[8][32];
    for (int i = t; i < 1024; i += 256) sWu[i] = g_pUp[i];
    __syncthreads();
    int warp = t >> 5, lane = t & 31;
    int n = (b - 5120) * 8 + warp;
    const float* f = nf + (size_t)n * 128;
    sF[warp][lane] = make_float4(f[lane], f[32 + 3 * lane],
                                 f[33 + 3 * lane], f[34 + 3 * lane]);
    __syncwarp();
    float os = 0.f, o0 = 0.f, o1 = 0.f, o2 = 0.f;
    #pragma unroll 8
    for (int m = 0; m < 32; m++) {
        float4 v = sF[warp][m];
        float2 w = sWu[m * 32 + lane];
        os = fmaf(v.x, w.x, os);
        o0 = fmaf(v.y, w.y, o0);
        o1 = fmaf(v.z, w.y, o1);
        o2 = fmaf(v.w, w.y, o2);
    }
    const float S = 0.17677669529663687f;
    ((float4*)g_up)[n * 32 + lane] = make_float4(os * S, o0 * S, o1 * S, o2 * S);
}

// ---------------------------------------------------------------------------
// K4 edge kernel: warp handles 32 receiver-sorted edges.
// SHFL-broadcast h (round-7 form), ballot run boundaries, register W_r2,
// and an 8-deep register prefetch ring for the sender gather (MLP=8).
// ST for interior runs, RED for window-straddling first/last runs.
// ---------------------------------------------------------------------------
__global__ void __launch_bounds__(256, 2)
edge_kernel(const float* __restrict__ W_r1, const float* __restrict__ W_r2,
            const float* __restrict__ esh, const float* __restrict__ rad) {
    int t = threadIdx.x, warp = t >> 5, lane = t & 31, j8 = lane & 7;
    int p0 = (blockIdx.x * 8 + warp) * 32;

    const float INV_SQRT8 = 0.3535533905932738f;
    const float SC = INV_SQRT8 * 0.25f;          // radial scale * AVG_NEIGH^-0.5
    const float INV_SQRT3 = 0.5773502691896258f;

    // register-resident W_r2, pre-scaled (SC on all; INV_SQRT3 folded into w_st)
    ull w2p01[8], w2p23[8];
    #pragma unroll
    for (int j = 0; j < 8; j++) {
        w2p01[j] = pk2(__ldg(&W_r2[j * 128 + lane]) * SC,
                       __ldg(&W_r2[j * 128 + 32 + lane]) * SC);
        w2p23[j] = pk2(__ldg(&W_r2[j * 128 + 64 + lane]) * SC,
                       __ldg(&W_r2[j * 128 + 96 + lane]) * SC * INV_SQRT3);
    }
    float W1r[8];
    #pragma unroll
    for (int k = 0; k < 8; k++) W1r[k] = __ldg(&W_r1[k * 8 + j8]);

    // full-warp header load (32 edges), then gather each edge's sh + radial
    int2 hdr = g_shdr[p0 + lane];
    int e = hdr.y & 0x3FFFF;
    float4 shq = __ldg(&((const float4*)esh)[e]);
    float4 rq0 = __ldg(&((const float4*)rad)[e * 2]);
    float4 rq1 = __ldg(&((const float4*)rad)[e * 2 + 1]);

    // run-boundary ballot (uniform across warp)
    int r = (int)(((unsigned)hdr.y) >> 18);
    int rprev = __shfl_up_sync(0xffffffffu, r, 1);
    unsigned bnd = __ballot_sync(0xffffffffu, (lane > 0) && (r != rprev));

    // batched radial MLP: 8 batches x 4 edges; lane = (e_loc = lane>>3, j = lane&7)
    int el4 = lane >> 3;
    float hb[8];
    #pragma unroll
    for (int b = 0; b < 8; b++) {
        int src = b * 4 + el4;
        float pre;
        pre = W1r[0] * __shfl_sync(0xffffffffu, rq0.x, src);
        pre = fmaf(W1r[1], __shfl_sync(0xffffffffu, rq0.y, src), pre);
        pre = fmaf(W1r[2], __shfl_sync(0xffffffffu, rq0.z, src), pre);
        pre = fmaf(W1r[3], __shfl_sync(0xffffffffu, rq0.w, src), pre);
        pre = fmaf(W1r[4], __shfl_sync(0xffffffffu, rq1.x, src), pre);
        pre = fmaf(W1r[5], __shfl_sync(0xffffffffu, rq1.y, src), pre);
        pre = fmaf(W1r[6], __shfl_sync(0xffffffffu, rq1.z, src), pre);
        pre = fmaf(W1r[7], __shfl_sync(0xffffffffu, rq1.w, src), pre);
        hb[b] = silu_f(pre * INV_SQRT8);
    }

    // prime the 8-deep sender-gather ring (MLP=8)
    float4 ring[8];
    #pragma unroll
    for (int q = 0; q < 8; q++) {
        int snd = __shfl_sync(0xffffffffu, hdr.x, q);
        ring[q] = __ldg(&((const float4*)g_up)[snd * 32 + lane]);
    }

    float aS0 = 0.f, aS1 = 0.f;
    float aV0l = 0.f, aV0h = 0.f, aV1l = 0.f, aV1h = 0.f, aV2l = 0.f, aV2h = 0.f;
    int nflush = 0;

    auto flushTo = [&](int node, bool useRed) {
        float* dst = g_acc + (size_t)node * 256 + lane * 8;
        if (useRed) {
            asm volatile("red.global.add.v4.f32 [%0], {%1,%2,%3,%4};"
                         :: "l"(dst), "f"(aS0), "f"(aS1), "f"(aV0l), "f"(aV0h) : "memory");
            asm volatile("red.global.add.v4.f32 [%0], {%1,%2,%3,%4};"
                         :: "l"(dst + 4), "f"(aV1l), "f"(aV1h), "f"(aV2l), "f"(aV2h) : "memory");
        } else {
            asm volatile("st.global.v4.f32 [%0], {%1,%2,%3,%4};"
                         :: "l"(dst), "f"(aS0), "f"(aS1), "f"(aV0l), "f"(aV0h) : "memory");
            asm volatile("st.global.v4.f32 [%0], {%1,%2,%3,%4};"
                         :: "l"(dst + 4), "f"(aV1l), "f"(aV1h), "f"(aV2l), "f"(aV2h) : "memory");
        }
    };

    #pragma unroll
    for (int i = 0; i < 32; i++) {
        if (i > 0 && ((bnd >> i) & 1u)) {
            int node = __shfl_sync(0xffffffffu, r, i - 1);
            flushTo(node, nflush == 0);   // first run may straddle backward -> RED
            nflush++;
            aS0 = aS1 = aV0l = aV0h = aV1l = aV1h = aV2l = aV2h = 0.f;
        }
        float4 u = ring[i & 7];
        if (i < 24) {                     // refill ring with edge i+8's gather
            int snd = __shfl_sync(0xffffffffu, hdr.x, i + 8);
            ring[i & 7] = __ldg(&((const float4*)g_up)[snd * 32 + lane]);
        }
        float y0 = __shfl_sync(0xffffffffu, shq.y, i);
        float y1 = __shfl_sync(0xffffffffu, shq.z, i);
        float y2 = __shfl_sync(0xffffffffu, shq.w, i);

        // w = h @ W_r2 (packed f32x2, j-broadcast form)
        ull w01 = 0ull, w23 = 0ull;
        float hbreg = hb[i >> 2];
        int hbase = (i & 3) * 8;
        #pragma unroll
        for (int j = 0; j < 8; j++) {
            float hj = __shfl_sync(0xffffffffu, hbreg, hbase + j);
            ull h2 = pk2(hj, hj);
            w01 = fma2_(h2, w2p01[j], w01);
            w23 = fma2_(h2, w2p23[j], w23);
        }
        float w0, w1, w2, w3;
        upk2(w0, w1, w01);
        upk2(w2, w3, w23);

        float dot = u.y * y0;
        dot = fmaf(u.z, y1, dot);
        dot = fmaf(u.w, y2, dot);
        float sst = u.x * w2;

        aS0  = fmaf(u.x, w0, aS0);
        aS1  = fmaf(dot, w3, aS1);
        aV0l = fmaf(u.y, w1, aV0l);  aV0h = fmaf(sst, y0, aV0h);
        aV1l = fmaf(u.z, w1, aV1l);  aV1h = fmaf(sst, y1, aV1h);
        aV2l = fmaf(u.w, w1, aV2l);  aV2h = fmaf(sst, y2, aV2h);
    }
    int lastnode = __shfl_sync(0xffffffffu, r, 31);
    flushTo(lastnode, true);   // last run may straddle forward -> RED
}

// ---------------------------------------------------------------------------
// K5 down-projection + skip + gating: 4 nodes per warp, __ldg weights,
// f32x2 accumulation. Also re-zeroes g_cnt for the next launch sequence.
// ---------------------------------------------------------------------------
__global__ void __launch_bounds__(128)
down_kernel(const float* __restrict__ nf,
            const int* __restrict__ species,
            float* __restrict__ out) {
    __shared__ float4 st[4][4][96];   // [warp][node][0:64 columns | 64:96 nf]
    int t = threadIdx.x, warp = t >> 5, lane = t & 31;
    int gid = blockIdx.x * 128 + t;
    if (gid < N_NODES) g_cnt[gid] = 0;     // restore invariant for next call
    int n0 = blockIdx.x * 16 + warp * 4;

    #pragma unroll
    for (int u = 0; u < 4; u++) {
        int n = n0 + u;
        const float4* a4 = (const float4*)g_acc + (size_t)n * 64;
        float4 qa = a4[lane * 2];
        float4 qb = a4[lane * 2 + 1];
        st[warp][u][lane]      = make_float4(qa.x, qa.z, qb.x, qb.z);  // cols m=lane
        st[warp][u][32 + lane] = make_float4(qa.y, qa.w, qb.y, qb.w);  // cols m=32+lane
        const float* f = nf + (size_t)n * 128;
        st[warp][u][64 + lane] = make_float4(f[lane], f[32 + 3 * lane],
                                             f[33 + 3 * lane], f[34 + 3 * lane]);
    }
    __syncwarp();

    const ull* w2p = (const ull*)g_pDn2;
    ull g01[4] = {0, 0, 0, 0}, gv[4] = {0, 0, 0, 0};
    float g4[4] = {0.f, 0.f, 0.f, 0.f};
    #pragma unroll 4
    for (int m = 0; m < 64; m++) {
        ull w2 = __ldg(&w2p[m * 32 + lane]);
        float wv = __ldg(&g_pDnV[m * 32 + lane]);
        ull wv2 = pk2(wv, wv);
        #pragma unroll
        for (int u = 0; u < 4; u++) {
            float4 b = st[warp][u][m];
            g01[u] = fma2_(pk2(b.x, b.x), w2, g01[u]);
            gv[u]  = fma2_(pk2(b.y, b.z), wv2, gv[u]);
            g4[u]  = fmaf(b.w, wv, g4[u]);
        }
    }

    int sp[4];
    #pragma unroll
    for (int u = 0; u < 4; u++) sp[u] = species[n0 + u];

    ull s01[4] = {0, 0, 0, 0}, sv[4] = {0, 0, 0, 0};
    float s4[4] = {0.f, 0.f, 0.f, 0.f};
    #pragma unroll 4
    for (int m = 0; m < 32; m++) {
        #pragma unroll
        for (int u = 0; u < 4; u++) {
            float4 w = __ldg(&g_pSk[sp[u] * 1024 + m * 32 + lane]);
            float4 c = st[warp][u][64 + m];
            s01[u] = fma2_(pk2(c.x, c.x), pk2(w.x, w.y), s01[u]);
            sv[u]  = fma2_(pk2(c.y, c.z), pk2(w.z, w.z), sv[u]);
            s4[u]  = fmaf(c.w, w.z, s4[u]);
        }
    }

    const float A = 0.5f * 0.125f;                 // 0.5 * (2*MUL)^-0.5
    const float B = 0.5f * 0.17677669529663687f;   // 0.5 * MUL^-0.5

    #pragma unroll
    for (int u = 0; u < 4; u++) {
        float G0, G1, H0, H1, S0, S1, T0, T1;
        upk2(G0, G1, g01[u]);
        upk2(H0, H1, gv[u]);
        upk2(S0, S1, s01[u]);
        upk2(T0, T1, sv[u]);
        G0 = G0 * A + S0 * B;
        G1 = G1 * A + S1 * B;
        H0 = H0 * A + T0 * B;
        H1 = H1 * A + T1 * B;
        float H2 = g4[u] * A + s4[u] * B;
        float feat = silu_f(G0);
        float gate = silu_f(G1);
        float* o = out + (size_t)(n0 + u) * 128;
        o[lane] = feat;
        o[32 + lane * 3 + 0] = H0 * gate;
        o[32 + lane * 3 + 1] = H1 * gate;
        o[32 + lane * 3 + 2] = H2 * gate;
    }
}

// ---------------------------------------------------------------------------
extern "C" void kernel_launch(void* const* d_in, const int* in_sizes, int n_in,
                              void* d_out, int out_size) {
    const float* nf  = (const float*)d_in[0];
    const float* esh = (const float*)d_in[1];
    const float* rad = (const float*)d_in[2];
    const float* Wus = (const float*)d_in[3];
    const float* Wuv = (const float*)d_in[4];
    const float* Wr1 = (const float*)d_in[5];
    const float* Wr2 = (const float*)d_in[6];
    const float* Wds = (const float*)d_in[7];
    const float* Wdv = (const float*)d_in[8];
    const float* Wss = (const float*)d_in[9];
    const float* Wsv = (const float*)d_in[10];
    const int* snd  = (const int*)d_in[11];
    const int* rcv  = (const int*)d_in[12];
    const int* spec = (const int*)d_in[13];
    float* out = (float*)d_out;

    prep_hist_kernel<<<1052, 256>>>(Wus, Wuv, Wds, Wdv, Wss, Wsv, rcv);
    scan_kernel<<<64, 256>>>();
    mid_kernel<<<7168, 256>>>(nf, rcv, snd);
    edge_kernel<<<1024, 256>>>(Wr1, Wr2, esh, rad);
    down_kernel<<<1024, 128>>>(nf, spec, out);
}

// round 10
// speedup vs baseline: 1.0858x; 1.0222x over previous
#include <cuda_runtime.h>

#define N_NODES 16384
#define N_EDGES 262144

typedef unsigned long long ull;

// ---------------------------------------------------------------------------
// Static device scratch (no runtime allocation). NOTE: g_cnt is zero at module
// load and re-zeroed by down_kernel at the end of every launch sequence, so
// hist can run in the first kernel without a separate zeroing pass.
// ---------------------------------------------------------------------------
__device__ float  g_up[N_NODES * 128];     // [n][lane][4] = (s1, v1x, v1y, v1z)
__device__ float  g_acc[N_NODES * 256];    // [n][lane][8] = (S0,S1,V0l,V0h,V1l,V1h,V2l,V2h)
__device__ int    g_cnt[N_NODES];
__device__ int    g_cursor[N_NODES];
__device__ int    g_base;
__device__ int2   g_shdr[N_EDGES];         // sorted header: (snd, rcv<<18 | e)
__device__ float2 g_pUp[1024];             // packed (W_up_s, W_up_v)
__device__ float2 g_pDn2[2048];            // packed (W_dn_s[m][k], W_dn_s[m][32+k])
__device__ float  g_pDnV[2048];            // W_dn_v[m][k]
__device__ float4 g_pSk[4096];             // packed skip weights per species

__device__ __forceinline__ float silu_f(float x) {
    return x / (1.0f + __expf(-x));
}

__device__ __forceinline__ ull pk2(float a, float b) {
    ull r; asm("mov.b64 %0, {%1,%2};" : "=l"(r) : "f"(a), "f"(b)); return r;
}
__device__ __forceinline__ void upk2(float& a, float& b, ull v) {
    asm("mov.b64 {%0,%1}, %2;" : "=f"(a), "=f"(b) : "l"(v));
}
__device__ __forceinline__ ull fma2_(ull a, ull b, ull c) {
    ull d; asm("fma.rn.f32x2 %0, %1, %2, %3;" : "=l"(d) : "l"(a), "l"(b), "l"(c)); return d;
}

// ---------------------------------------------------------------------------
// K1: weight packing (blocks 0..27) + receiver histogram (blocks 28..1051).
// ---------------------------------------------------------------------------
__global__ void __launch_bounds__(256)
prep_hist_kernel(const float* __restrict__ Wus, const float* __restrict__ Wuv,
                 const float* __restrict__ Wds, const float* __restrict__ Wdv,
                 const float* __restrict__ Wss, const float* __restrict__ Wsv,
                 const int* __restrict__ rcv) {
    int b = blockIdx.x;
    if (b >= 28) {
        int e = (b - 28) * 256 + threadIdx.x;
        atomicAdd(&g_cnt[rcv[e]], 1);
        return;
    }
    int t = b * 256 + threadIdx.x;
    if (t == 0) g_base = 0;
    if (t < 1024) g_pUp[t] = make_float2(Wus[t], Wuv[t]);
    int i = t - 1024;
    if (i >= 0 && i < 2048) {
        int m = i >> 5, k = i & 31;
        g_pDn2[i] = make_float2(Wds[m * 64 + k], Wds[m * 64 + 32 + k]);
        g_pDnV[i] = Wdv[i];
    }
    int j = t - 3072;
    if (j >= 0 && j < 4096) {
        int sp = j >> 10, q = j & 1023, m = q >> 5, k = q & 31;
        g_pSk[j] = make_float4(Wss[sp * 2048 + m * 64 + k],
                               Wss[sp * 2048 + m * 64 + 32 + k],
                               Wsv[sp * 1024 + q], 0.f);
    }
}

// ---------------------------------------------------------------------------
// K2 parallel scan: block-local scan + atomic global base
// ---------------------------------------------------------------------------
__global__ void __launch_bounds__(256) scan_kernel() {
    __shared__ int sWarp[8];
    __shared__ int sBase;
    int t = threadIdx.x;
    int lane = t & 31, warp = t >> 5;
    int n = blockIdx.x * 256 + t;
    int c = g_cnt[n];
    int incl = c;
    #pragma unroll
    for (int o = 1; o < 32; o <<= 1) {
        int v = __shfl_up_sync(0xffffffffu, incl, o);
        if (lane >= o) incl += v;
    }
    if (lane == 31) sWarp[warp] = incl;
    __syncthreads();
    if (t < 8) {
        int v = sWarp[t];
        #pragma unroll
        for (int o = 1; o < 8; o <<= 1) {
            int u = __shfl_up_sync(0xffu, v, o);
            if (t >= o) v += u;
        }
        sWarp[t] = v;
        if (t == 7) sBase = atomicAdd(&g_base, v);
    }
    __syncthreads();
    int warpBase = (warp > 0) ? sWarp[warp - 1] : 0;
    g_cursor[n] = sBase + warpBase + incl - c;
}

// ---------------------------------------------------------------------------
// K3 fused: scatter (blocks 0..1023) + zero_acc (1024..5119) + up (5120..7167)
// ---------------------------------------------------------------------------
__global__ void __launch_bounds__(256)
mid_kernel(const float* __restrict__ nf,
           const int* __restrict__ receivers, const int* __restrict__ senders) {
    int b = blockIdx.x;
    int t = threadIdx.x;
    if (b < 1024) {                                   // 8B-header scatter
        int e = b * 256 + t;
        int r = receivers[e];
        int s = senders[e];
        int p = atomicAdd(&g_cursor[r], 1);
        g_shdr[p] = make_int2(s, (r << 18) | e);
        return;
    }
    if (b < 5120) {                                   // zero accumulator (16 MB)
        ((float4*)g_acc)[(b - 1024) * 256 + t] = make_float4(0.f, 0.f, 0.f, 0.f);
        return;
    }
    // up-projection: 8 nodes per block (warp per node), packed weights
    __shared__ float2 sWu[1024];
    __shared__ float4 sF[8][32];
    for (int i = t; i < 1024; i += 256) sWu[i] = g_pUp[i];
    __syncthreads();
    int warp = t >> 5, lane = t & 31;
    int n = (b - 5120) * 8 + warp;
    const float* f = nf + (size_t)n * 128;
    sF[warp][lane] = make_float4(f[lane], f[32 + 3 * lane],
                                 f[33 + 3 * lane], f[34 + 3 * lane]);
    __syncwarp();
    float os = 0.f, o0 = 0.f, o1 = 0.f, o2 = 0.f;
    #pragma unroll 8
    for (int m = 0; m < 32; m++) {
        float4 v = sF[warp][m];
        float2 w = sWu[m * 32 + lane];
        os = fmaf(v.x, w.x, os);
        o0 = fmaf(v.y, w.y, o0);
        o1 = fmaf(v.z, w.y, o1);
        o2 = fmaf(v.w, w.y, o2);
    }
    const float S = 0.17677669529663687f;
    ((float4*)g_up)[n * 32 + lane] = make_float4(os * S, o0 * S, o1 * S, o2 * S);
}

// ---------------------------------------------------------------------------
// K4 edge kernel: warp handles 32 receiver-sorted edges.
// MLP computes 2 h-values/lane, stores PRE-PACKED pairs to SMEM (STS.64);
// inner loop reads h via 2 uniform LDS.128 (no shuffles, no packing) and y via
// 1 uniform LDS.128. Pair-dot matvec: 4 independent fma2 chains of depth 4.
// 8-deep register prefetch ring for the sender gather. Ballot run boundaries;
// ST interior runs, RED window-straddling first/last runs.
// ---------------------------------------------------------------------------
__global__ void __launch_bounds__(256, 2)
edge_kernel(const float* __restrict__ W_r1, const float* __restrict__ W_r2,
            const float* __restrict__ esh, const float* __restrict__ rad) {
    __shared__ float4 sHY[8][32];     // per warp: (unused, y0, y1, y2) per edge
    __shared__ ull    sHp[8][128];    // per warp: h pairs, 4 ull per edge
    int t = threadIdx.x, warp = t >> 5, lane = t & 31;
    int p0 = (blockIdx.x * 8 + warp) * 32;

    const float INV_SQRT8 = 0.3535533905932738f;
    const float SC = INV_SQRT8 * 0.25f;          // radial scale * AVG_NEIGH^-0.5
    const float INV_SQRT3 = 0.5773502691896258f;

    // wp[p][c] = (W2[2p][c*32+lane], W2[2p+1][c*32+lane]) * scale_c
    // (c==3 column carries INV_SQRT3)
    ull wp[4][4];
    #pragma unroll
    for (int p = 0; p < 4; p++) {
        #pragma unroll
        for (int c = 0; c < 4; c++) {
            float scc = (c == 3) ? SC * INV_SQRT3 : SC;
            wp[p][c] = pk2(__ldg(&W_r2[(2 * p) * 128 + c * 32 + lane]) * scc,
                           __ldg(&W_r2[(2 * p + 1) * 128 + c * 32 + lane]) * scc);
        }
    }
    // W1 columns for this lane's j-pair (j = 2j', 2j'+1 with j' = lane&3)
    int j2 = (lane & 3) * 2;
    float W1a[8], W1b[8];
    #pragma unroll
    for (int k = 0; k < 8; k++) {
        W1a[k] = __ldg(&W_r1[k * 8 + j2]);
        W1b[k] = __ldg(&W_r1[k * 8 + j2 + 1]);
    }

    // full-warp header load (32 edges), then gather each edge's sh + radial
    int2 hdr = g_shdr[p0 + lane];
    int e = hdr.y & 0x3FFFF;
    float4 shq = __ldg(&((const float4*)esh)[e]);
    float4 rq0 = __ldg(&((const float4*)rad)[e * 2]);
    float4 rq1 = __ldg(&((const float4*)rad)[e * 2 + 1]);
    sHY[warp][lane] = make_float4(0.f, shq.y, shq.z, shq.w);

    // run-boundary ballot (uniform across warp)
    int r = (int)(((unsigned)hdr.y) >> 18);
    int rprev = __shfl_up_sync(0xffffffffu, r, 1);
    unsigned bnd = __ballot_sync(0xffffffffu, (lane > 0) && (r != rprev));

    // batched radial MLP: 4 batches x 8 edges; lane = (e_loc = lane>>2, j' = lane&3)
    // each lane computes h[E][2j'] and h[E][2j'+1], stores packed pair.
    int el = lane >> 2;
    #pragma unroll
    for (int b = 0; b < 4; b++) {
        int src = b * 8 + el;
        float rk, preA, preB;
        rk = __shfl_sync(0xffffffffu, rq0.x, src); preA = rk * W1a[0]; preB = rk * W1b[0];
        rk = __shfl_sync(0xffffffffu, rq0.y, src); preA = fmaf(rk, W1a[1], preA); preB = fmaf(rk, W1b[1], preB);
        rk = __shfl_sync(0xffffffffu, rq0.z, src); preA = fmaf(rk, W1a[2], preA); preB = fmaf(rk, W1b[2], preB);
        rk = __shfl_sync(0xffffffffu, rq0.w, src); preA = fmaf(rk, W1a[3], preA); preB = fmaf(rk, W1b[3], preB);
        rk = __shfl_sync(0xffffffffu, rq1.x, src); preA = fmaf(rk, W1a[4], preA); preB = fmaf(rk, W1b[4], preB);
        rk = __shfl_sync(0xffffffffu, rq1.y, src); preA = fmaf(rk, W1a[5], preA); preB = fmaf(rk, W1b[5], preB);
        rk = __shfl_sync(0xffffffffu, rq1.z, src); preA = fmaf(rk, W1a[6], preA); preB = fmaf(rk, W1b[6], preB);
        rk = __shfl_sync(0xffffffffu, rq1.w, src); preA = fmaf(rk, W1a[7], preA); preB = fmaf(rk, W1b[7], preB);
        float hA = silu_f(preA * INV_SQRT8);
        float hB = silu_f(preB * INV_SQRT8);
        // slot index = E*4 + j' = b*32 + lane  (contiguous, conflict-free)
        sHp[warp][b * 32 + lane] = pk2(hA, hB);
    }
    __syncwarp();

    // prime the 8-deep sender-gather ring (MLP=8)
    const float4* upL = (const float4*)g_up + lane;
    float4 ring[8];
    #pragma unroll
    for (int q = 0; q < 8; q++) {
        int snd = __shfl_sync(0xffffffffu, hdr.x, q);
        ring[q] = __ldg(&upL[snd * 32]);
    }

    float aS0 = 0.f, aS1 = 0.f;
    float aV0l = 0.f, aV0h = 0.f, aV1l = 0.f, aV1h = 0.f, aV2l = 0.f, aV2h = 0.f;
    int nflush = 0;

    auto flushTo = [&](int node, bool useRed) {
        float* dst = g_acc + (size_t)node * 256 + lane * 8;
        if (useRed) {
            asm volatile("red.global.add.v4.f32 [%0], {%1,%2,%3,%4};"
                         :: "l"(dst), "f"(aS0), "f"(aS1), "f"(aV0l), "f"(aV0h) : "memory");
            asm volatile("red.global.add.v4.f32 [%0], {%1,%2,%3,%4};"
                         :: "l"(dst + 4), "f"(aV1l), "f"(aV1h), "f"(aV2l), "f"(aV2h) : "memory");
        } else {
            asm volatile("st.global.v4.f32 [%0], {%1,%2,%3,%4};"
                         :: "l"(dst), "f"(aS0), "f"(aS1), "f"(aV0l), "f"(aV0h) : "memory");
            asm volatile("st.global.v4.f32 [%0], {%1,%2,%3,%4};"
                         :: "l"(dst + 4), "f"(aV1l), "f"(aV1h), "f"(aV2l), "f"(aV2h) : "memory");
        }
    };

    const ulonglong2* hp2 = (const ulonglong2*)sHp[warp];

    #pragma unroll
    for (int i = 0; i < 32; i++) {
        if (i > 0 && ((bnd >> i) & 1u)) {
            int node = __shfl_sync(0xffffffffu, r, i - 1);
            flushTo(node, nflush == 0);   // first run may straddle backward -> RED
            nflush++;
            aS0 = aS1 = aV0l = aV0h = aV1l = aV1h = aV2l = aV2h = 0.f;
        }
        float4 u = ring[i & 7];
        if (i < 24) {                     // refill ring with edge i+8's gather
            int snd = __shfl_sync(0xffffffffu, hdr.x, i + 8);
            ring[i & 7] = __ldg(&upL[snd * 32]);
        }
        float4 hy = sHY[warp][i];                    // uniform LDS.128 (y0,y1,y2)
        ulonglong2 v1 = hp2[i * 2];                  // h pairs (0,1),(2,3)
        ulonglong2 v2 = hp2[i * 2 + 1];              // h pairs (4,5),(6,7)

        ull a0 = 0, a1 = 0, a2 = 0, a3 = 0;          // 4 independent chains, depth 4
        a0 = fma2_(v1.x, wp[0][0], a0); a1 = fma2_(v1.x, wp[0][1], a1);
        a2 = fma2_(v1.x, wp[0][2], a2); a3 = fma2_(v1.x, wp[0][3], a3);
        a0 = fma2_(v1.y, wp[1][0], a0); a1 = fma2_(v1.y, wp[1][1], a1);
        a2 = fma2_(v1.y, wp[1][2], a2); a3 = fma2_(v1.y, wp[1][3], a3);
        a0 = fma2_(v2.x, wp[2][0], a0); a1 = fma2_(v2.x, wp[2][1], a1);
        a2 = fma2_(v2.x, wp[2][2], a2); a3 = fma2_(v2.x, wp[2][3], a3);
        a0 = fma2_(v2.y, wp[3][0], a0); a1 = fma2_(v2.y, wp[3][1], a1);
        a2 = fma2_(v2.y, wp[3][2], a2); a3 = fma2_(v2.y, wp[3][3], a3);

        float w0, w1, w2, w3, lo, hi;
        upk2(lo, hi, a0); w0 = lo + hi;
        upk2(lo, hi, a1); w1 = lo + hi;
        upk2(lo, hi, a2); w2 = lo + hi;
        upk2(lo, hi, a3); w3 = lo + hi;

        float dot = u.y * hy.y;
        dot = fmaf(u.z, hy.z, dot);
        dot = fmaf(u.w, hy.w, dot);
        float sst = u.x * w2;

        aS0  = fmaf(u.x, w0, aS0);
        aS1  = fmaf(dot, w3, aS1);
        aV0l = fmaf(u.y, w1, aV0l);  aV0h = fmaf(sst, hy.y, aV0h);
        aV1l = fmaf(u.z, w1, aV1l);  aV1h = fmaf(sst, hy.z, aV1h);
        aV2l = fmaf(u.w, w1, aV2l);  aV2h = fmaf(sst, hy.w, aV2h);
    }
    int lastnode = __shfl_sync(0xffffffffu, r, 31);
    flushTo(lastnode, true);   // last run may straddle forward -> RED
}

// ---------------------------------------------------------------------------
// K5 down-projection + skip + gating: 4 nodes per warp, __ldg weights,
// f32x2 accumulation. Also re-zeroes g_cnt for the next launch sequence.
// ---------------------------------------------------------------------------
__global__ void __launch_bounds__(128)
down_kernel(const float* __restrict__ nf,
            const int* __restrict__ species,
            float* __restrict__ out) {
    __shared__ float4 st[4][4][96];   // [warp][node][0:64 columns | 64:96 nf]
    int t = threadIdx.x, warp = t >> 5, lane = t & 31;
    int gid = blockIdx.x * 128 + t;
    if (gid < N_NODES) g_cnt[gid] = 0;     // restore invariant for next call
    int n0 = blockIdx.x * 16 + warp * 4;

    #pragma unroll
    for (int u = 0; u < 4; u++) {
        int n = n0 + u;
        const float4* a4 = (const float4*)g_acc + (size_t)n * 64;
        float4 qa = a4[lane * 2];
        float4 qb = a4[lane * 2 + 1];
        st[warp][u][lane]      = make_float4(qa.x, qa.z, qb.x, qb.z);  // cols m=lane
        st[warp][u][32 + lane] = make_float4(qa.y, qa.w, qb.y, qb.w);  // cols m=32+lane
        const float* f = nf + (size_t)n * 128;
        st[warp][u][64 + lane] = make_float4(f[lane], f[32 + 3 * lane],
                                             f[33 + 3 * lane], f[34 + 3 * lane]);
    }
    __syncwarp();

    const ull* w2p = (const ull*)g_pDn2;
    ull g01[4] = {0, 0, 0, 0}, gv[4] = {0, 0, 0, 0};
    float g4[4] = {0.f, 0.f, 0.f, 0.f};
    #pragma unroll 4
    for (int m = 0; m < 64; m++) {
        ull w2 = __ldg(&w2p[m * 32 + lane]);
        float wv = __ldg(&g_pDnV[m * 32 + lane]);
        ull wv2 = pk2(wv, wv);
        #pragma unroll
        for (int u = 0; u < 4; u++) {
            float4 b = st[warp][u][m];
            g01[u] = fma2_(pk2(b.x, b.x), w2, g01[u]);
            gv[u]  = fma2_(pk2(b.y, b.z), wv2, gv[u]);
            g4[u]  = fmaf(b.w, wv, g4[u]);
        }
    }

    int sp[4];
    #pragma unroll
    for (int u = 0; u < 4; u++) sp[u] = species[n0 + u];

    ull s01[4] = {0, 0, 0, 0}, sv[4] = {0, 0, 0, 0};
    float s4[4] = {0.f, 0.f, 0.f, 0.f};
    #pragma unroll 4
    for (int m = 0; m < 32; m++) {
        #pragma unroll
        for (int u = 0; u < 4; u++) {
            float4 w = __ldg(&g_pSk[sp[u] * 1024 + m * 32 + lane]);
            float4 c = st[warp][u][64 + m];
            s01[u] = fma2_(pk2(c.x, c.x), pk2(w.x, w.y), s01[u]);
            sv[u]  = fma2_(pk2(c.y, c.z), pk2(w.z, w.z), sv[u]);
            s4[u]  = fmaf(c.w, w.z, s4[u]);
        }
    }

    const float A = 0.5f * 0.125f;                 // 0.5 * (2*MUL)^-0.5
    const float B = 0.5f * 0.17677669529663687f;   // 0.5 * MUL^-0.5

    #pragma unroll
    for (int u = 0; u < 4; u++) {
        float G0, G1, H0, H1, S0, S1, T0, T1;
        upk2(G0, G1, g01[u]);
        upk2(H0, H1, gv[u]);
        upk2(S0, S1, s01[u]);
        upk2(T0, T1, sv[u]);
        G0 = G0 * A + S0 * B;
        G1 = G1 * A + S1 * B;
        H0 = H0 * A + T0 * B;
        H1 = H1 * A + T1 * B;
        float H2 = g4[u] * A + s4[u] * B;
        float feat = silu_f(G0);
        float gate = silu_f(G1);
        float* o = out + (size_t)(n0 + u) * 128;
        o[lane] = feat;
        o[32 + lane * 3 + 0] = H0 * gate;
        o[32 + lane * 3 + 1] = H1 * gate;
        o[32 + lane * 3 + 2] = H2 * gate;
    }
}

// ---------------------------------------------------------------------------
extern "C" void kernel_launch(void* const* d_in, const int* in_sizes, int n_in,
                              void* d_out, int out_size) {
    const float* nf  = (const float*)d_in[0];
    const float* esh = (const float*)d_in[1];
    const float* rad = (const float*)d_in[2];
    const float* Wus = (const float*)d_in[3];
    const float* Wuv = (const float*)d_in[4];
    const float* Wr1 = (const float*)d_in[5];
    const float* Wr2 = (const float*)d_in[6];
    const float* Wds = (const float*)d_in[7];
    const float* Wdv = (const float*)d_in[8];
    const float* Wss = (const float*)d_in[9];
    const float* Wsv = (const float*)d_in[10];
    const int* snd  = (const int*)d_in[11];
    const int* rcv  = (const int*)d_in[12];
    const int* spec = (const int*)d_in[13];
    float* out = (float*)d_out;

    prep_hist_kernel<<<1052, 256>>>(Wus, Wuv, Wds, Wdv, Wss, Wsv, rcv);
    scan_kernel<<<64, 256>>>();
    mid_kernel<<<7168, 256>>>(nf, rcv, snd);
    edge_kernel<<<1024, 256>>>(Wr1, Wr2, esh, rad);
    down_kernel<<<1024, 128>>>(nf, spec, out);
}

// round 11
// speedup vs baseline: 1.0900x; 1.0039x over previous
#include <cuda_runtime.h>

#define N_NODES 16384
#define N_EDGES 262144

typedef unsigned long long ull;

// ---------------------------------------------------------------------------
// Static device scratch (no runtime allocation). NOTE: g_cnt is zero at module
// load and re-zeroed by down_kernel at the end of every launch sequence, so
// hist can run in the first kernel without a separate zeroing pass.
// ---------------------------------------------------------------------------
__device__ float  g_up[N_NODES * 128];     // [n][lane][4] = (s1, v1x, v1y, v1z)
__device__ float  g_acc[N_NODES * 256];    // [n][lane][8] = (S0,S1,V0l,V0h,V1l,V1h,V2l,V2h)
__device__ int    g_cnt[N_NODES];
__device__ int    g_cursor[N_NODES];
__device__ int    g_base;
__device__ int2   g_shdr[N_EDGES];         // sorted header: (snd, rcv<<18 | e)
__device__ float2 g_pUp[1024];             // packed (W_up_s, W_up_v)
__device__ float2 g_pDn2[2048];            // packed (W_dn_s[m][k], W_dn_s[m][32+k])
__device__ float  g_pDnV[2048];            // W_dn_v[m][k]
__device__ float4 g_pSk[4096];             // packed skip weights per species

__device__ __forceinline__ float silu_f(float x) {
    return x / (1.0f + __expf(-x));
}

__device__ __forceinline__ ull pk2(float a, float b) {
    ull r; asm("mov.b64 %0, {%1,%2};" : "=l"(r) : "f"(a), "f"(b)); return r;
}
__device__ __forceinline__ void upk2(float& a, float& b, ull v) {
    asm("mov.b64 {%0,%1}, %2;" : "=f"(a), "=f"(b) : "l"(v));
}
__device__ __forceinline__ ull fma2_(ull a, ull b, ull c) {
    ull d; asm("fma.rn.f32x2 %0, %1, %2, %3;" : "=l"(d) : "l"(a), "l"(b), "l"(c)); return d;
}

// ---------------------------------------------------------------------------
// K1: weight packing (blocks 0..27) + receiver histogram (blocks 28..539,
// 2 edges per thread, vectorized int2 loads).
// ---------------------------------------------------------------------------
__global__ void __launch_bounds__(256)
prep_hist_kernel(const float* __restrict__ Wus, const float* __restrict__ Wuv,
                 const float* __restrict__ Wds, const float* __restrict__ Wdv,
                 const float* __restrict__ Wss, const float* __restrict__ Wsv,
                 const int* __restrict__ rcv) {
    int b = blockIdx.x;
    if (b >= 28) {
        int i = (b - 28) * 256 + threadIdx.x;          // i in [0, 131072)
        int2 rr = ((const int2*)rcv)[i];
        atomicAdd(&g_cnt[rr.x], 1);
        atomicAdd(&g_cnt[rr.y], 1);
        return;
    }
    int t = b * 256 + threadIdx.x;
    if (t == 0) g_base = 0;
    if (t < 1024) g_pUp[t] = make_float2(Wus[t], Wuv[t]);
    int i = t - 1024;
    if (i >= 0 && i < 2048) {
        int m = i >> 5, k = i & 31;
        g_pDn2[i] = make_float2(Wds[m * 64 + k], Wds[m * 64 + 32 + k]);
        g_pDnV[i] = Wdv[i];
    }
    int j = t - 3072;
    if (j >= 0 && j < 4096) {
        int sp = j >> 10, q = j & 1023, m = q >> 5, k = q & 31;
        g_pSk[j] = make_float4(Wss[sp * 2048 + m * 64 + k],
                               Wss[sp * 2048 + m * 64 + 32 + k],
                               Wsv[sp * 1024 + q], 0.f);
    }
}

// ---------------------------------------------------------------------------
// K2 parallel scan: block-local scan + atomic global base
// ---------------------------------------------------------------------------
__global__ void __launch_bounds__(256) scan_kernel() {
    __shared__ int sWarp[8];
    __shared__ int sBase;
    int t = threadIdx.x;
    int lane = t & 31, warp = t >> 5;
    int n = blockIdx.x * 256 + t;
    int c = g_cnt[n];
    int incl = c;
    #pragma unroll
    for (int o = 1; o < 32; o <<= 1) {
        int v = __shfl_up_sync(0xffffffffu, incl, o);
        if (lane >= o) incl += v;
    }
    if (lane == 31) sWarp[warp] = incl;
    __syncthreads();
    if (t < 8) {
        int v = sWarp[t];
        #pragma unroll
        for (int o = 1; o < 8; o <<= 1) {
            int u = __shfl_up_sync(0xffu, v, o);
            if (t >= o) v += u;
        }
        sWarp[t] = v;
        if (t == 7) sBase = atomicAdd(&g_base, v);
    }
    __syncthreads();
    int warpBase = (warp > 0) ? sWarp[warp - 1] : 0;
    g_cursor[n] = sBase + warpBase + incl - c;
}

// ---------------------------------------------------------------------------
// K3 fused: scatter 2 edges/thread (blocks 0..511) + zero_acc (512..4607)
//           + up (4608..6655)
// ---------------------------------------------------------------------------
__global__ void __launch_bounds__(256)
mid_kernel(const float* __restrict__ nf,
           const int* __restrict__ receivers, const int* __restrict__ senders) {
    int b = blockIdx.x;
    int t = threadIdx.x;
    if (b < 512) {                                    // 8B-header scatter, x2
        int i = b * 256 + t;
        int2 rr = ((const int2*)receivers)[i];
        int2 ss = ((const int2*)senders)[i];
        int e0 = i * 2;
        int p0 = atomicAdd(&g_cursor[rr.x], 1);
        int p1 = atomicAdd(&g_cursor[rr.y], 1);
        g_shdr[p0] = make_int2(ss.x, (rr.x << 18) | e0);
        g_shdr[p1] = make_int2(ss.y, (rr.y << 18) | (e0 + 1));
        return;
    }
    if (b < 4608) {                                   // zero accumulator (16 MB)
        ((float4*)g_acc)[(b - 512) * 256 + t] = make_float4(0.f, 0.f, 0.f, 0.f);
        return;
    }
    // up-projection: 8 nodes per block (warp per node), packed weights
    __shared__ float2 sWu[1024];
    __shared__ float4 sF[8][32];
    for (int i = t; i < 1024; i += 256) sWu[i] = g_pUp[i];
    __syncthreads();
    int warp = t >> 5, lane = t & 31;
    int n = (b - 4608) * 8 + warp;
    const float* f = nf + (size_t)n * 128;
    sF[warp][lane] = make_float4(f[lane], f[32 + 3 * lane],
                                 f[33 + 3 * lane], f[34 + 3 * lane]);
    __syncwarp();
    float os = 0.f, o0 = 0.f, o1 = 0.f, o2 = 0.f;
    #pragma unroll 8
    for (int m = 0; m < 32; m++) {
        float4 v = sF[warp][m];
        float2 w = sWu[m * 32 + lane];
        os = fmaf(v.x, w.x, os);
        o0 = fmaf(v.y, w.y, o0);
        o1 = fmaf(v.z, w.y, o1);
        o2 = fmaf(v.w, w.y, o2);
    }
    const float S = 0.17677669529663687f;
    ((float4*)g_up)[n * 32 + lane] = make_float4(os * S, o0 * S, o1 * S, o2 * S);
}

// ---------------------------------------------------------------------------
// K4 edge kernel: warp handles 32 receiver-sorted edges. 128-thread blocks,
// 5 blocks/SM (20 warps). MLP computes 2 h-values/lane, stores pre-packed
// pairs (STS.64); inner loop: 2 uniform LDS.128 for h, 1 for y; pair-dot
// matvec (4 independent fma2 chains of depth 4); 6-deep register prefetch
// ring for the sender gather. Ballot run boundaries; ST interior runs,
// RED window-straddling first/last runs.
// ---------------------------------------------------------------------------
__global__ void __launch_bounds__(128, 5)
edge_kernel(const float* __restrict__ W_r1, const float* __restrict__ W_r2,
            const float* __restrict__ esh, const float* __restrict__ rad) {
    __shared__ float4 sHY[4][32];     // per warp: (unused, y0, y1, y2) per edge
    __shared__ ull    sHp[4][128];    // per warp: h pairs, 4 ull per edge
    int t = threadIdx.x, warp = t >> 5, lane = t & 31;
    int p0 = (blockIdx.x * 4 + warp) * 32;

    const float INV_SQRT8 = 0.3535533905932738f;
    const float SC = INV_SQRT8 * 0.25f;          // radial scale * AVG_NEIGH^-0.5
    const float INV_SQRT3 = 0.5773502691896258f;

    // wp[p][c] = (W2[2p][c*32+lane], W2[2p+1][c*32+lane]) * scale_c
    ull wp[4][4];
    #pragma unroll
    for (int p = 0; p < 4; p++) {
        #pragma unroll
        for (int c = 0; c < 4; c++) {
            float scc = (c == 3) ? SC * INV_SQRT3 : SC;
            wp[p][c] = pk2(__ldg(&W_r2[(2 * p) * 128 + c * 32 + lane]) * scc,
                           __ldg(&W_r2[(2 * p + 1) * 128 + c * 32 + lane]) * scc);
        }
    }
    // W1 columns for this lane's j-pair (j = 2j', 2j'+1 with j' = lane&3)
    int j2 = (lane & 3) * 2;
    float W1a[8], W1b[8];
    #pragma unroll
    for (int k = 0; k < 8; k++) {
        W1a[k] = __ldg(&W_r1[k * 8 + j2]);
        W1b[k] = __ldg(&W_r1[k * 8 + j2 + 1]);
    }

    // full-warp header load (32 edges), then gather each edge's sh + radial
    int2 hdr = g_shdr[p0 + lane];
    int e = hdr.y & 0x3FFFF;
    float4 shq = __ldg(&((const float4*)esh)[e]);
    float4 rq0 = __ldg(&((const float4*)rad)[e * 2]);
    float4 rq1 = __ldg(&((const float4*)rad)[e * 2 + 1]);
    sHY[warp][lane] = make_float4(0.f, shq.y, shq.z, shq.w);

    // run-boundary ballot (uniform across warp)
    int r = (int)(((unsigned)hdr.y) >> 18);
    int rprev = __shfl_up_sync(0xffffffffu, r, 1);
    unsigned bnd = __ballot_sync(0xffffffffu, (lane > 0) && (r != rprev));

    // batched radial MLP: 4 batches x 8 edges; lane = (e_loc = lane>>2, j' = lane&3)
    int el = lane >> 2;
    #pragma unroll
    for (int b = 0; b < 4; b++) {
        int src = b * 8 + el;
        float rk, preA, preB;
        rk = __shfl_sync(0xffffffffu, rq0.x, src); preA = rk * W1a[0]; preB = rk * W1b[0];
        rk = __shfl_sync(0xffffffffu, rq0.y, src); preA = fmaf(rk, W1a[1], preA); preB = fmaf(rk, W1b[1], preB);
        rk = __shfl_sync(0xffffffffu, rq0.z, src); preA = fmaf(rk, W1a[2], preA); preB = fmaf(rk, W1b[2], preB);
        rk = __shfl_sync(0xffffffffu, rq0.w, src); preA = fmaf(rk, W1a[3], preA); preB = fmaf(rk, W1b[3], preB);
        rk = __shfl_sync(0xffffffffu, rq1.x, src); preA = fmaf(rk, W1a[4], preA); preB = fmaf(rk, W1b[4], preB);
        rk = __shfl_sync(0xffffffffu, rq1.y, src); preA = fmaf(rk, W1a[5], preA); preB = fmaf(rk, W1b[5], preB);
        rk = __shfl_sync(0xffffffffu, rq1.z, src); preA = fmaf(rk, W1a[6], preA); preB = fmaf(rk, W1b[6], preB);
        rk = __shfl_sync(0xffffffffu, rq1.w, src); preA = fmaf(rk, W1a[7], preA); preB = fmaf(rk, W1b[7], preB);
        float hA = silu_f(preA * INV_SQRT8);
        float hB = silu_f(preB * INV_SQRT8);
        sHp[warp][b * 32 + lane] = pk2(hA, hB);   // slot = E*4 + j'
    }
    __syncwarp();

    // prime the 6-deep sender-gather ring (MLP=6)
    const float4* upL = (const float4*)g_up + lane;
    float4 ring[6];
    #pragma unroll
    for (int q = 0; q < 6; q++) {
        int snd = __shfl_sync(0xffffffffu, hdr.x, q);
        ring[q] = __ldg(&upL[snd * 32]);
    }

    float aS0 = 0.f, aS1 = 0.f;
    float aV0l = 0.f, aV0h = 0.f, aV1l = 0.f, aV1h = 0.f, aV2l = 0.f, aV2h = 0.f;
    int nflush = 0;

    auto flushTo = [&](int node, bool useRed) {
        float* dst = g_acc + (size_t)node * 256 + lane * 8;
        if (useRed) {
            asm volatile("red.global.add.v4.f32 [%0], {%1,%2,%3,%4};"
                         :: "l"(dst), "f"(aS0), "f"(aS1), "f"(aV0l), "f"(aV0h) : "memory");
            asm volatile("red.global.add.v4.f32 [%0], {%1,%2,%3,%4};"
                         :: "l"(dst + 4), "f"(aV1l), "f"(aV1h), "f"(aV2l), "f"(aV2h) : "memory");
        } else {
            asm volatile("st.global.v4.f32 [%0], {%1,%2,%3,%4};"
                         :: "l"(dst), "f"(aS0), "f"(aS1), "f"(aV0l), "f"(aV0h) : "memory");
            asm volatile("st.global.v4.f32 [%0], {%1,%2,%3,%4};"
                         :: "l"(dst + 4), "f"(aV1l), "f"(aV1h), "f"(aV2l), "f"(aV2h) : "memory");
        }
    };

    const ulonglong2* hp2 = (const ulonglong2*)sHp[warp];

    #pragma unroll
    for (int i = 0; i < 32; i++) {
        if (i > 0 && ((bnd >> i) & 1u)) {
            int node = __shfl_sync(0xffffffffu, r, i - 1);
            flushTo(node, nflush == 0);   // first run may straddle backward -> RED
            nflush++;
            aS0 = aS1 = aV0l = aV0h = aV1l = aV1h = aV2l = aV2h = 0.f;
        }
        float4 u = ring[i % 6];
        if (i < 26) {                     // refill ring with edge i+6's gather
            int snd = __shfl_sync(0xffffffffu, hdr.x, i + 6);
            ring[i % 6] = __ldg(&upL[snd * 32]);
        }
        float4 hy = sHY[warp][i];                    // uniform LDS.128 (y0,y1,y2)
        ulonglong2 v1 = hp2[i * 2];                  // h pairs (0,1),(2,3)
        ulonglong2 v2 = hp2[i * 2 + 1];              // h pairs (4,5),(6,7)

        ull a0 = 0, a1 = 0, a2 = 0, a3 = 0;          // 4 independent chains, depth 4
        a0 = fma2_(v1.x, wp[0][0], a0); a1 = fma2_(v1.x, wp[0][1], a1);
        a2 = fma2_(v1.x, wp[0][2], a2); a3 = fma2_(v1.x, wp[0][3], a3);
        a0 = fma2_(v1.y, wp[1][0], a0); a1 = fma2_(v1.y, wp[1][1], a1);
        a2 = fma2_(v1.y, wp[1][2], a2); a3 = fma2_(v1.y, wp[1][3], a3);
        a0 = fma2_(v2.x, wp[2][0], a0); a1 = fma2_(v2.x, wp[2][1], a1);
        a2 = fma2_(v2.x, wp[2][2], a2); a3 = fma2_(v2.x, wp[2][3], a3);
        a0 = fma2_(v2.y, wp[3][0], a0); a1 = fma2_(v2.y, wp[3][1], a1);
        a2 = fma2_(v2.y, wp[3][2], a2); a3 = fma2_(v2.y, wp[3][3], a3);

        float w0, w1, w2, w3, lo, hi;
        upk2(lo, hi, a0); w0 = lo + hi;
        upk2(lo, hi, a1); w1 = lo + hi;
        upk2(lo, hi, a2); w2 = lo + hi;
        upk2(lo, hi, a3); w3 = lo + hi;

        float dot = u.y * hy.y;
        dot = fmaf(u.z, hy.z, dot);
        dot = fmaf(u.w, hy.w, dot);
        float sst = u.x * w2;

        aS0  = fmaf(u.x, w0, aS0);
        aS1  = fmaf(dot, w3, aS1);
        aV0l = fmaf(u.y, w1, aV0l);  aV0h = fmaf(sst, hy.y, aV0h);
        aV1l = fmaf(u.z, w1, aV1l);  aV1h = fmaf(sst, hy.z, aV1h);
        aV2l = fmaf(u.w, w1, aV2l);  aV2h = fmaf(sst, hy.w, aV2h);
    }
    int lastnode = __shfl_sync(0xffffffffu, r, 31);
    flushTo(lastnode, true);   // last run may straddle forward -> RED
}

// ---------------------------------------------------------------------------
// K5 down-projection + skip + gating: 4 nodes per warp, __ldg weights,
// f32x2 accumulation. Also re-zeroes g_cnt for the next launch sequence.
// ---------------------------------------------------------------------------
__global__ void __launch_bounds__(128)
down_kernel(const float* __restrict__ nf,
            const int* __restrict__ species,
            float* __restrict__ out) {
    __shared__ float4 st[4][4][96];   // [warp][node][0:64 columns | 64:96 nf]
    int t = threadIdx.x, warp = t >> 5, lane = t & 31;
    int gid = blockIdx.x * 128 + t;
    if (gid < N_NODES) g_cnt[gid] = 0;     // restore invariant for next call
    int n0 = blockIdx.x * 16 + warp * 4;

    #pragma unroll
    for (int u = 0; u < 4; u++) {
        int n = n0 + u;
        const float4* a4 = (const float4*)g_acc + (size_t)n * 64;
        float4 qa = a4[lane * 2];
        float4 qb = a4[lane * 2 + 1];
        st[warp][u][lane]      = make_float4(qa.x, qa.z, qb.x, qb.z);  // cols m=lane
        st[warp][u][32 + lane] = make_float4(qa.y, qa.w, qb.y, qb.w);  // cols m=32+lane
        const float* f = nf + (size_t)n * 128;
        st[warp][u][64 + lane] = make_float4(f[lane], f[32 + 3 * lane],
                                             f[33 + 3 * lane], f[34 + 3 * lane]);
    }
    __syncwarp();

    const ull* w2p = (const ull*)g_pDn2;
    ull g01[4] = {0, 0, 0, 0}, gv[4] = {0, 0, 0, 0};
    float g4[4] = {0.f, 0.f, 0.f, 0.f};
    #pragma unroll 4
    for (int m = 0; m < 64; m++) {
        ull w2 = __ldg(&w2p[m * 32 + lane]);
        float wv = __ldg(&g_pDnV[m * 32 + lane]);
        ull wv2 = pk2(wv, wv);
        #pragma unroll
        for (int u = 0; u < 4; u++) {
            float4 b = st[warp][u][m];
            g01[u] = fma2_(pk2(b.x, b.x), w2, g01[u]);
            gv[u]  = fma2_(pk2(b.y, b.z), wv2, gv[u]);
            g4[u]  = fmaf(b.w, wv, g4[u]);
        }
    }

    int sp[4];
    #pragma unroll
    for (int u = 0; u < 4; u++) sp[u] = species[n0 + u];

    ull s01[4] = {0, 0, 0, 0}, sv[4] = {0, 0, 0, 0};
    float s4[4] = {0.f, 0.f, 0.f, 0.f};
    #pragma unroll 4
    for (int m = 0; m < 32; m++) {
        #pragma unroll
        for (int u = 0; u < 4; u++) {
            float4 w = __ldg(&g_pSk[sp[u] * 1024 + m * 32 + lane]);
            float4 c = st[warp][u][64 + m];
            s01[u] = fma2_(pk2(c.x, c.x), pk2(w.x, w.y), s01[u]);
            sv[u]  = fma2_(pk2(c.y, c.z), pk2(w.z, w.z), sv[u]);
            s4[u]  = fmaf(c.w, w.z, s4[u]);
        }
    }

    const float A = 0.5f * 0.125f;                 // 0.5 * (2*MUL)^-0.5
    const float B = 0.5f * 0.17677669529663687f;   // 0.5 * MUL^-0.5

    #pragma unroll
    for (int u = 0; u < 4; u++) {
        float G0, G1, H0, H1, S0, S1, T0, T1;
        upk2(G0, G1, g01[u]);
        upk2(H0, H1, gv[u]);
        upk2(S0, S1, s01[u]);
        upk2(T0, T1, sv[u]);
        G0 = G0 * A + S0 * B;
        G1 = G1 * A + S1 * B;
        H0 = H0 * A + T0 * B;
        H1 = H1 * A + T1 * B;
        float H2 = g4[u] * A + s4[u] * B;
        float feat = silu_f(G0);
        float gate = silu_f(G1);
        float* o = out + (size_t)(n0 + u) * 128;
        o[lane] = feat;
        o[32 + lane * 3 + 0] = H0 * gate;
        o[32 + lane * 3 + 1] = H1 * gate;
        o[32 + lane * 3 + 2] = H2 * gate;
    }
}

// ---------------------------------------------------------------------------
extern "C" void kernel_launch(void* const* d_in, const int* in_sizes, int n_in,
                              void* d_out, int out_size) {
    const float* nf  = (const float*)d_in[0];
    const float* esh = (const float*)d_in[1];
    const float* rad = (const float*)d_in[2];
    const float* Wus = (const float*)d_in[3];
    const float* Wuv = (const float*)d_in[4];
    const float* Wr1 = (const float*)d_in[5];
    const float* Wr2 = (const float*)d_in[6];
    const float* Wds = (const float*)d_in[7];
    const float* Wdv = (const float*)d_in[8];
    const float* Wss = (const float*)d_in[9];
    const float* Wsv = (const float*)d_in[10];
    const int* snd  = (const int*)d_in[11];
    const int* rcv  = (const int*)d_in[12];
    const int* spec = (const int*)d_in[13];
    float* out = (float*)d_out;

    prep_hist_kernel<<<540, 256>>>(Wus, Wuv, Wds, Wdv, Wss, Wsv, rcv);
    scan_kernel<<<64, 256>>>();
    mid_kernel<<<6656, 256>>>(nf, rcv, snd);
    edge_kernel<<<2048, 128>>>(Wr1, Wr2, esh, rad);
    down_kernel<<<1024, 128>>>(nf, spec, out);
}